// round 14
// baseline (speedup 1.0000x reference)
#include <cuda_runtime.h>

// AdderNet: out[n,h,w,f] = sum_{dh,dw,c} |Xpad[n,h+dh-1,w+dw-1,c] - F[f,dh,dw,c]|
// X [8,32,32,32] f32 NHWC, F [64,3,3,32] f32, out [8,32,32,64] f32.
//
// R14: s16 quantized core using PTX vabsdiff2.s32.s32.s32.add:
//   one instruction = 2x (diff + abs) + horizontal add + accumulate.
//   Scale 4096 (2^12): max |val| ~4.6 -> 18.8k << 32767; acc <= ~11M << 2^31;
//   quantization rel err ~5e-6. Exact integer accumulation -> no flushes.
// Tile 4px x 1f, block 128 = wq(8) x fg(16), grid (256 nh, 4 fq).
// X smem swizzle s = r*9+q (wp = 4q+r): 128B-contiguous x-loads.
// Filter stride 37 chunks: conflict-free broadcast loads.

#define XS_CH (3 * 4 * 36)          // 432 chunks (16B = 8 channels s16)
#define FSTRIDE 37
#define FS_CH (16 * FSTRIDE)        // 592 chunks
#define SMEM_BYTES ((XS_CH + FS_CH) * 16)   // 16,384 B

#define QS 4096.0f
#define INV_QS (1.0f / 4096.0f)

struct __align__(16) I2x4 { unsigned a, b, c, d; };   // 8 s16 channels

__device__ __forceinline__ unsigned pack_q2(float x, float y) {
    int i0 = __float2int_rn(x * QS);
    int i1 = __float2int_rn(y * QS);
    return __byte_perm((unsigned)i0, (unsigned)i1, 0x5410);
}

__device__ __forceinline__ I2x4 cvt_chunk(float4 lo, float4 hi) {
    I2x4 r;
    r.a = pack_q2(lo.x, lo.y);
    r.b = pack_q2(lo.z, lo.w);
    r.c = pack_q2(hi.x, hi.y);
    r.d = pack_q2(hi.z, hi.w);
    return r;
}

// acc += |a.h0-b.h0| + |a.h1-b.h1|   (signed 16-bit halves, one instruction)
__device__ __forceinline__ int vad2(int acc, unsigned a, unsigned b) {
    int r;
    asm("vabsdiff2.s32.s32.s32.add %0, %1, %2, %3;"
        : "=r"(r) : "r"(a), "r"(b), "r"(acc));
    return r;
}

// acc += sum over 24 terms (3 taps x 8 channels)
__device__ __forceinline__ int l1_24i(
    int acc, const I2x4& xa, const I2x4& xb, const I2x4& xc,
    const I2x4& f0, const I2x4& f1, const I2x4& f2) {
    acc = vad2(acc, xa.a, f0.a);
    acc = vad2(acc, xa.b, f0.b);
    acc = vad2(acc, xa.c, f0.c);
    acc = vad2(acc, xa.d, f0.d);
    acc = vad2(acc, xb.a, f1.a);
    acc = vad2(acc, xb.b, f1.b);
    acc = vad2(acc, xb.c, f1.c);
    acc = vad2(acc, xb.d, f1.d);
    acc = vad2(acc, xc.a, f2.a);
    acc = vad2(acc, xc.b, f2.b);
    acc = vad2(acc, xc.c, f2.c);
    acc = vad2(acc, xc.d, f2.d);
    return acc;
}

__global__ __launch_bounds__(128, 7)
void adder_layer_kernel(const float* __restrict__ X,
                        const float* __restrict__ Fw,
                        float* __restrict__ out) {
    extern __shared__ __align__(16) I2x4 smem[];
    I2x4* Xs = smem;                  // [(dh*4 + c8)*36 + s], s = r*9+q, wp = 4q+r
    I2x4* Fs = smem + XS_CH;          // [fl*37 + (dh*3+dw)*4 + c8]

    const int tid = threadIdx.x;
    const int nh = blockIdx.x;        // n*32 + h
    const int fbase = blockIdx.y * 16;
    const int n = nh >> 5;
    const int h = nh & 31;

    const float4* Xg4 = reinterpret_cast<const float4*>(X);
    const float4* Fg4 = reinterpret_cast<const float4*>(Fw);

    // ---- Filter fill: fp32 -> s16 chunks ----
    for (int i = tid; i < 16 * 36; i += 128) {
        int fl = i / 36;
        int j = i - fl * 36;          // (dh*3+dw)*4 + c8
        int g = ((fbase + fl) * 36 + j) * 2;
        Fs[fl * FSTRIDE + j] = cvt_chunk(Fg4[g], Fg4[g + 1]);
    }

    // ---- X fill: 3 rows, swizzled, zero-padded, fp32 -> s16 ----
    for (int i = tid; i < XS_CH; i += 128) {
        int c8 = i & 3;
        int t = i >> 2;
        int s = t % 36;
        int dh = t / 36;
        int q = s % 9, r = s / 9;
        int wp = 4 * q + r;
        int row = h - 1 + dh;
        int w = wp - 1;
        I2x4 v;
        if (row >= 0 && row < 32 && w >= 0 && w < 32) {
            int g = ((((n * 32) + row) * 32 + w) * 8 + c8 * 2);
            v = cvt_chunk(Xg4[g], Xg4[g + 1]);
        } else {
            v.a = 0u; v.b = 0u; v.c = 0u; v.d = 0u;
        }
        Xs[(dh * 4 + c8) * 36 + s] = v;
    }
    __syncthreads();

    const int wq = tid & 7;           // pixels w = 4wq .. 4wq+3
    const int fg = tid >> 3;          // 0..15 -> filter fbase + fg

    int acc0 = 0, acc1 = 0, acc2 = 0, acc3 = 0;   // exact integer accumulators

    const I2x4* Fb = Fs + fg * FSTRIDE;

    #pragma unroll
    for (int kk = 0; kk < 12; kk++) {             // kk = dh*4 + c8
        const int dh = kk >> 2;
        const int c8 = kk & 3;
        const int j0 = dh * 12 + c8;              // tap dw=0; dw steps +4

        // x: 8 channels at wp = 4wq + k, k = 0..5
        const I2x4* xr = Xs + kk * 36 + wq;
        I2x4 x0 = xr[0];
        I2x4 x1 = xr[9];
        I2x4 x2 = xr[18];
        I2x4 x3 = xr[27];
        I2x4 x4 = xr[1];
        I2x4 x5 = xr[10];

        // filter taps for this filter: 3 dw
        I2x4 f0 = Fb[j0], f1 = Fb[j0 + 4], f2 = Fb[j0 + 8];

        // per pixel p: taps see x[p], x[p+1], x[p+2]
        acc0 = l1_24i(acc0, x0, x1, x2, f0, f1, f2);
        acc1 = l1_24i(acc1, x1, x2, x3, f0, f1, f2);
        acc2 = l1_24i(acc2, x2, x3, x4, f0, f1, f2);
        acc3 = l1_24i(acc3, x3, x4, x5, f0, f1, f2);
    }

    // ---- Epilogue: rescale, scalar store per pixel ----
    float* obase = out + ((nh * 32) + 4 * wq) * 64 + fbase + fg;
    obase[0]   = (float)acc0 * INV_QS;
    obase[64]  = (float)acc1 * INV_QS;
    obase[128] = (float)acc2 * INV_QS;
    obase[192] = (float)acc3 * INV_QS;
}

extern "C" void kernel_launch(void* const* d_in, const int* in_sizes, int n_in,
                              void* d_out, int out_size) {
    const float* X = (const float*)d_in[0];
    const float* Fw = (const float*)d_in[1];
    float* out = (float*)d_out;

    cudaFuncSetAttribute(adder_layer_kernel,
                         cudaFuncAttributeMaxDynamicSharedMemorySize, SMEM_BYTES);
    dim3 grid(256, 4);
    adder_layer_kernel<<<grid, 128, SMEM_BYTES>>>(X, Fw, out);
}

// round 15
// speedup vs baseline: 4.1328x; 4.1328x over previous
#include <cuda_runtime.h>
#include <cuda_fp16.h>

// AdderNet: out[n,h,w,f] = sum_{dh,dw,c} |Xpad[n,h+dh-1,w+dw-1,c] - F[f,dh,dw,c]|
// X [8,32,32,32] f32 NHWC, F [64,3,3,32] f32, out [8,32,32,64] f32.
//
// R15: R13 fp16 core with FLAT dependency shape:
//  - 16 independent half2 accumulator chains (4px x 4 fields), no merge tree
//    in the hot loop (fp32 kernels with flat chains issued at 53-55% vs fp16
//    tree's 44%).
//  - abs = single LOP (and.b32 0x7FFF7FFF) -> alu pipe, balancing fma/alu.
//  - per-dh: one-shot 16->4 merge + fp32 flush (rel_err ~2e-4).
// Tile 4px x 1f, block 128 = wq(8) x fg(16), grid (256 nh, 4 fq) = 1024 CTAs.
// X smem swizzle s = r*9+q (wp = 4q+r); filter stride 37 chunks.

#define XS_CH (3 * 4 * 36)          // 432 chunks (16B = 8 channels fp16)
#define FSTRIDE 37
#define FS_CH (16 * FSTRIDE)        // 592 chunks
#define SMEM_BYTES ((XS_CH + FS_CH) * 16)   // 16,384 B

struct __align__(16) H2x4 { __half2 a, b, c, d; };

__device__ __forceinline__ H2x4 cvt_chunk(float4 lo, float4 hi) {
    H2x4 r;
    r.a = __float22half2_rn(make_float2(lo.x, lo.y));
    r.b = __float22half2_rn(make_float2(lo.z, lo.w));
    r.c = __float22half2_rn(make_float2(hi.x, hi.y));
    r.d = __float22half2_rn(make_float2(hi.z, hi.w));
    return r;
}

// |v| on both fp16 lanes via one 32-bit AND (alu pipe, 1 instr)
__device__ __forceinline__ __half2 habs_u(__half2 v) {
    unsigned u;
    asm("and.b32 %0, %1, 0x7FFF7FFF;" : "=r"(u)
        : "r"(*reinterpret_cast<unsigned*>(&v)));
    return *reinterpret_cast<__half2*>(&u);
}

// One pixel's 12 terms for this kk: 3 taps x 4 fields into 4 independent chains
#define PXUPD(p, xa, xb, xc)                                              \
    cA##p = __hadd2(cA##p, habs_u(__hsub2((xa).a, f0.a)));                \
    cB##p = __hadd2(cB##p, habs_u(__hsub2((xa).b, f0.b)));                \
    cC##p = __hadd2(cC##p, habs_u(__hsub2((xa).c, f0.c)));                \
    cD##p = __hadd2(cD##p, habs_u(__hsub2((xa).d, f0.d)));                \
    cA##p = __hadd2(cA##p, habs_u(__hsub2((xb).a, f1.a)));                \
    cB##p = __hadd2(cB##p, habs_u(__hsub2((xb).b, f1.b)));                \
    cC##p = __hadd2(cC##p, habs_u(__hsub2((xb).c, f1.c)));                \
    cD##p = __hadd2(cD##p, habs_u(__hsub2((xb).d, f1.d)));                \
    cA##p = __hadd2(cA##p, habs_u(__hsub2((xc).a, f2.a)));                \
    cB##p = __hadd2(cB##p, habs_u(__hsub2((xc).b, f2.b)));                \
    cC##p = __hadd2(cC##p, habs_u(__hsub2((xc).c, f2.c)));                \
    cD##p = __hadd2(cD##p, habs_u(__hsub2((xc).d, f2.d)))

#define FLUSH(p)                                                          \
    {                                                                     \
        __half2 m = __hadd2(__hadd2(cA##p, cB##p), __hadd2(cC##p, cD##p));\
        float2 t = __half22float2(m);                                     \
        acc##p.x += t.x; acc##p.y += t.y;                                 \
        cA##p = hz; cB##p = hz; cC##p = hz; cD##p = hz;                   \
    }

__global__ __launch_bounds__(128, 7)
void adder_layer_kernel(const float* __restrict__ X,
                        const float* __restrict__ Fw,
                        float* __restrict__ out) {
    extern __shared__ __align__(16) H2x4 smem[];
    H2x4* Xs = smem;                  // [(dh*4 + c8)*36 + s], s = r*9+q, wp = 4q+r
    H2x4* Fs = smem + XS_CH;          // [fl*37 + (dh*3+dw)*4 + c8]

    const int tid = threadIdx.x;
    const int nh = blockIdx.x;        // n*32 + h
    const int fbase = blockIdx.y * 16;
    const int n = nh >> 5;
    const int h = nh & 31;

    const float4* Xg4 = reinterpret_cast<const float4*>(X);
    const float4* Fg4 = reinterpret_cast<const float4*>(Fw);

    // ---- Filter fill: fp32 -> fp16 chunks ----
    for (int i = tid; i < 16 * 36; i += 128) {
        int fl = i / 36;
        int j = i - fl * 36;          // (dh*3+dw)*4 + c8
        int g = ((fbase + fl) * 36 + j) * 2;
        Fs[fl * FSTRIDE + j] = cvt_chunk(Fg4[g], Fg4[g + 1]);
    }

    // ---- X fill: 3 rows, swizzled, zero-padded, fp32 -> fp16 ----
    for (int i = tid; i < XS_CH; i += 128) {
        int c8 = i & 3;
        int t = i >> 2;
        int s = t % 36;
        int dh = t / 36;
        int q = s % 9, r = s / 9;
        int wp = 4 * q + r;
        int row = h - 1 + dh;
        int w = wp - 1;
        H2x4 v;
        if (row >= 0 && row < 32 && w >= 0 && w < 32) {
            int g = ((((n * 32) + row) * 32 + w) * 8 + c8 * 2);
            v = cvt_chunk(Xg4[g], Xg4[g + 1]);
        } else {
            __half2 z = __float2half2_rn(0.f);
            v.a = z; v.b = z; v.c = z; v.d = z;
        }
        Xs[(dh * 4 + c8) * 36 + s] = v;
    }
    __syncthreads();

    const int wq = tid & 7;           // pixels w = 4wq .. 4wq+3
    const int fg = tid >> 3;          // 0..15 -> filter fbase + fg

    const __half2 hz = __float2half2_rn(0.f);
    float2 acc0 = make_float2(0.f, 0.f), acc1 = make_float2(0.f, 0.f);
    float2 acc2 = make_float2(0.f, 0.f), acc3 = make_float2(0.f, 0.f);

    // 16 independent fp16 chains: [pixel 0..3][field A..D]
    __half2 cA0 = hz, cB0 = hz, cC0 = hz, cD0 = hz;
    __half2 cA1 = hz, cB1 = hz, cC1 = hz, cD1 = hz;
    __half2 cA2 = hz, cB2 = hz, cC2 = hz, cD2 = hz;
    __half2 cA3 = hz, cB3 = hz, cC3 = hz, cD3 = hz;

    const H2x4* Fb = Fs + fg * FSTRIDE;

    #pragma unroll
    for (int dh = 0; dh < 3; dh++) {
        #pragma unroll
        for (int c8 = 0; c8 < 4; c8++) {
            const int kk = dh * 4 + c8;
            const int j0 = dh * 12 + c8;

            const H2x4* xr = Xs + kk * 36 + wq;
            H2x4 x0 = xr[0];
            H2x4 x1 = xr[9];
            H2x4 x2 = xr[18];
            H2x4 x3 = xr[27];
            H2x4 x4 = xr[1];
            H2x4 x5 = xr[10];

            H2x4 f0 = Fb[j0], f1 = Fb[j0 + 4], f2 = Fb[j0 + 8];

            PXUPD(0, x0, x1, x2);
            PXUPD(1, x1, x2, x3);
            PXUPD(2, x2, x3, x4);
            PXUPD(3, x3, x4, x5);
        }
        // one-shot merge + fp32 flush per dh (chain partials <= ~14)
        FLUSH(0); FLUSH(1); FLUSH(2); FLUSH(3);
    }

    // ---- Epilogue: combine packed lanes, scalar store per pixel ----
    float* obase = out + ((nh * 32) + 4 * wq) * 64 + fbase + fg;
    obase[0]   = acc0.x + acc0.y;
    obase[64]  = acc1.x + acc1.y;
    obase[128] = acc2.x + acc2.y;
    obase[192] = acc3.x + acc3.y;
}

extern "C" void kernel_launch(void* const* d_in, const int* in_sizes, int n_in,
                              void* d_out, int out_size) {
    const float* X = (const float*)d_in[0];
    const float* Fw = (const float*)d_in[1];
    float* out = (float*)d_out;

    cudaFuncSetAttribute(adder_layer_kernel,
                         cudaFuncAttributeMaxDynamicSharedMemorySize, SMEM_BYTES);
    dim3 grid(256, 4);
    adder_layer_kernel<<<grid, 128, SMEM_BYTES>>>(X, Fw, out);
}

// round 16
// speedup vs baseline: 4.2456x; 1.0273x over previous
#include <cuda_runtime.h>
#include <cuda_fp16.h>

// AdderNet: out[n,h,w,f] = sum_{dh,dw,c} |Xpad[n,h+dh-1,w+dw-1,c] - F[f,dh,dw,c]|
// X [8,32,32,32] f32 NHWC, F [64,3,3,32] f32, out [8,32,32,64] f32.
//
// R16: R15's 16 flat accumulator chains + R13's foldable abs:
//   acc = hadd2(acc, habs2(hsub2(x,f))) -> SASS "HADD2 acc, |d|, acc":
//   2 fma-pipe instrs per 2 elems, NO alu-pipe abs. Fewest instructions
//   (R13 level) at the best dependency shape (R15 level).
// Tile 4px x 1f, block 128 = wq(8) x fg(16), grid (256 nh, 4 fq) = 1024 CTAs.
// X smem swizzle s = r*9+q (wp = 4q+r); filter stride 37 chunks.
// Per-dh fp32 flush (rel_err ~1.4e-4).

#define XS_CH (3 * 4 * 36)          // 432 chunks (16B = 8 channels fp16)
#define FSTRIDE 37
#define FS_CH (16 * FSTRIDE)        // 592 chunks
#define SMEM_BYTES ((XS_CH + FS_CH) * 16)   // 16,384 B

struct __align__(16) H2x4 { __half2 a, b, c, d; };

__device__ __forceinline__ H2x4 cvt_chunk(float4 lo, float4 hi) {
    H2x4 r;
    r.a = __float22half2_rn(make_float2(lo.x, lo.y));
    r.b = __float22half2_rn(make_float2(lo.z, lo.w));
    r.c = __float22half2_rn(make_float2(hi.x, hi.y));
    r.d = __float22half2_rn(make_float2(hi.z, hi.w));
    return r;
}

// One pixel's 12 terms for this kk: 3 taps x 4 fields -> 4 independent chains.
// __habs2 result feeds HADD2 as |src| operand modifier (folded by ptxas).
#define PXUPD(p, xa, xb, xc)                                              \
    cA##p = __hadd2(cA##p, __habs2(__hsub2((xa).a, f0.a)));               \
    cB##p = __hadd2(cB##p, __habs2(__hsub2((xa).b, f0.b)));               \
    cC##p = __hadd2(cC##p, __habs2(__hsub2((xa).c, f0.c)));               \
    cD##p = __hadd2(cD##p, __habs2(__hsub2((xa).d, f0.d)));               \
    cA##p = __hadd2(cA##p, __habs2(__hsub2((xb).a, f1.a)));               \
    cB##p = __hadd2(cB##p, __habs2(__hsub2((xb).b, f1.b)));               \
    cC##p = __hadd2(cC##p, __habs2(__hsub2((xb).c, f1.c)));               \
    cD##p = __hadd2(cD##p, __habs2(__hsub2((xb).d, f1.d)));               \
    cA##p = __hadd2(cA##p, __habs2(__hsub2((xc).a, f2.a)));               \
    cB##p = __hadd2(cB##p, __habs2(__hsub2((xc).b, f2.b)));               \
    cC##p = __hadd2(cC##p, __habs2(__hsub2((xc).c, f2.c)));               \
    cD##p = __hadd2(cD##p, __habs2(__hsub2((xc).d, f2.d)))

#define FLUSH(p)                                                          \
    {                                                                     \
        __half2 m = __hadd2(__hadd2(cA##p, cB##p), __hadd2(cC##p, cD##p));\
        float2 t = __half22float2(m);                                     \
        acc##p.x += t.x; acc##p.y += t.y;                                 \
        cA##p = hz; cB##p = hz; cC##p = hz; cD##p = hz;                   \
    }

__global__ __launch_bounds__(128, 7)
void adder_layer_kernel(const float* __restrict__ X,
                        const float* __restrict__ Fw,
                        float* __restrict__ out) {
    extern __shared__ __align__(16) H2x4 smem[];
    H2x4* Xs = smem;                  // [(dh*4 + c8)*36 + s], s = r*9+q, wp = 4q+r
    H2x4* Fs = smem + XS_CH;          // [fl*37 + (dh*3+dw)*4 + c8]

    const int tid = threadIdx.x;
    const int nh = blockIdx.x;        // n*32 + h
    const int fbase = blockIdx.y * 16;
    const int n = nh >> 5;
    const int h = nh & 31;

    const float4* Xg4 = reinterpret_cast<const float4*>(X);
    const float4* Fg4 = reinterpret_cast<const float4*>(Fw);

    // ---- Filter fill: fp32 -> fp16 chunks ----
    for (int i = tid; i < 16 * 36; i += 128) {
        int fl = i / 36;
        int j = i - fl * 36;          // (dh*3+dw)*4 + c8
        int g = ((fbase + fl) * 36 + j) * 2;
        Fs[fl * FSTRIDE + j] = cvt_chunk(Fg4[g], Fg4[g + 1]);
    }

    // ---- X fill: 3 rows, swizzled, zero-padded, fp32 -> fp16 ----
    for (int i = tid; i < XS_CH; i += 128) {
        int c8 = i & 3;
        int t = i >> 2;
        int s = t % 36;
        int dh = t / 36;
        int q = s % 9, r = s / 9;
        int wp = 4 * q + r;
        int row = h - 1 + dh;
        int w = wp - 1;
        H2x4 v;
        if (row >= 0 && row < 32 && w >= 0 && w < 32) {
            int g = ((((n * 32) + row) * 32 + w) * 8 + c8 * 2);
            v = cvt_chunk(Xg4[g], Xg4[g + 1]);
        } else {
            __half2 z = __float2half2_rn(0.f);
            v.a = z; v.b = z; v.c = z; v.d = z;
        }
        Xs[(dh * 4 + c8) * 36 + s] = v;
    }
    __syncthreads();

    const int wq = tid & 7;           // pixels w = 4wq .. 4wq+3
    const int fg = tid >> 3;          // 0..15 -> filter fbase + fg

    const __half2 hz = __float2half2_rn(0.f);
    float2 acc0 = make_float2(0.f, 0.f), acc1 = make_float2(0.f, 0.f);
    float2 acc2 = make_float2(0.f, 0.f), acc3 = make_float2(0.f, 0.f);

    // 16 independent fp16 chains: [pixel 0..3][field A..D]
    __half2 cA0 = hz, cB0 = hz, cC0 = hz, cD0 = hz;
    __half2 cA1 = hz, cB1 = hz, cC1 = hz, cD1 = hz;
    __half2 cA2 = hz, cB2 = hz, cC2 = hz, cD2 = hz;
    __half2 cA3 = hz, cB3 = hz, cC3 = hz, cD3 = hz;

    const H2x4* Fb = Fs + fg * FSTRIDE;

    #pragma unroll
    for (int dh = 0; dh < 3; dh++) {
        #pragma unroll
        for (int c8 = 0; c8 < 4; c8++) {
            const int kk = dh * 4 + c8;
            const int j0 = dh * 12 + c8;

            const H2x4* xr = Xs + kk * 36 + wq;
            H2x4 x0 = xr[0];
            H2x4 x1 = xr[9];
            H2x4 x2 = xr[18];
            H2x4 x3 = xr[27];
            H2x4 x4 = xr[1];
            H2x4 x5 = xr[10];

            H2x4 f0 = Fb[j0], f1 = Fb[j0 + 4], f2 = Fb[j0 + 8];

            PXUPD(0, x0, x1, x2);
            PXUPD(1, x1, x2, x3);
            PXUPD(2, x2, x3, x4);
            PXUPD(3, x3, x4, x5);
        }
        // one-shot merge + fp32 flush per dh (chain partials <= ~14)
        FLUSH(0); FLUSH(1); FLUSH(2); FLUSH(3);
    }

    // ---- Epilogue: combine packed lanes, scalar store per pixel ----
    float* obase = out + ((nh * 32) + 4 * wq) * 64 + fbase + fg;
    obase[0]   = acc0.x + acc0.y;
    obase[64]  = acc1.x + acc1.y;
    obase[128] = acc2.x + acc2.y;
    obase[192] = acc3.x + acc3.y;
}

extern "C" void kernel_launch(void* const* d_in, const int* in_sizes, int n_in,
                              void* d_out, int out_size) {
    const float* X = (const float*)d_in[0];
    const float* Fw = (const float*)d_in[1];
    float* out = (float*)d_out;

    cudaFuncSetAttribute(adder_layer_kernel,
                         cudaFuncAttributeMaxDynamicSharedMemorySize, SMEM_BYTES);
    dim3 grid(256, 4);
    adder_layer_kernel<<<grid, 128, SMEM_BYTES>>>(X, Fw, out);
}